// round 5
// baseline (speedup 1.0000x reference)
#include <cuda_runtime.h>
#include <math.h>
#include <stdint.h>

#define NTOK   2048
#define DMODEL 2048
#define KVD    512
#define NHEADS 16
#define HDIM   128

static __device__ float g_Q[NTOK * DMODEL];
static __device__ float g_K[NTOK * KVD];
static __device__ float g_V[NTOK * KVD];
static __device__ float g_S[(size_t)NHEADS * NTOK * NTOK];
static __device__ float g_C[NTOK * DMODEL];
static __device__ float g_partial[(size_t)NHEADS * 16 * NTOK];  // per (head, coltile, row)
static __device__ float g_inv[NHEADS * NTOK];                   // 1/rowsum

#define SMEM_WORDS (9216 + 2 * 4608)     // As0,As1 (2*4608) + Bs0,Bs1 (max 2*4608)
#define SMEM_BYTES (SMEM_WORDS * 4)      // 73728

__device__ __forceinline__ uint32_t f2tf32(float x) {
    uint32_t r;
    asm("cvt.rna.tf32.f32 %0, %1;" : "=r"(r) : "f"(x));
    return r;
}

__device__ __forceinline__ void mma_tf32(float c[4], const uint32_t a[4],
                                         uint32_t b0, uint32_t b1) {
    asm volatile(
        "mma.sync.aligned.m16n8k8.row.col.f32.tf32.tf32.f32 "
        "{%0,%1,%2,%3}, {%4,%5,%6,%7}, {%8,%9}, {%0,%1,%2,%3};"
        : "+f"(c[0]), "+f"(c[1]), "+f"(c[2]), "+f"(c[3])
        : "r"(a[0]), "r"(a[1]), "r"(a[2]), "r"(a[3]), "r"(b0), "r"(b1));
}

// ---------------------------------------------------------------------------
// TF32 tensor-core GEMM, 128x128 block tile, 256 threads (8 warps, 4m x 2n),
// warp tile 32x64, K chunk 32, double-buffered smem (1 sync per chunk).
// BT=false: C = A(MxK) @ B(KxN) (B row-major). BT=true: C = A @ B^T (B NxK).
// MODE 0: plain store. MODE 1 (qk): exp(scale*acc) + causal mask + row
// partial sums -> partialOut[localrow]. MODE 2 (pv): acc *= invsum[localrow].
// ---------------------------------------------------------------------------
template <bool BT, int MODE>
__device__ __forceinline__ void tf32gemm(const float* __restrict__ A,
                                         const float* __restrict__ B,
                                         float* __restrict__ C,
                                         int nChunks, int lda, int ldb, int ldc,
                                         float* __restrict__ partialOut,
                                         const float* __restrict__ invsum,
                                         int rowg0, int colg0)
{
    extern __shared__ uint32_t sm[];
    uint32_t* Asb[2] = { sm, sm + 4608 };
    const int BSZ = BT ? 4608 : 4224;
    uint32_t* Bsb[2] = { sm + 9216, sm + 9216 + BSZ };

    const int tid  = threadIdx.x;
    const int lane = tid & 31, wid = tid >> 5;
    const int wm = wid & 3, wn = wid >> 2;
    const int g = lane >> 2, t = lane & 3;

    float acc[2][8][4];
#pragma unroll
    for (int mt = 0; mt < 2; ++mt)
#pragma unroll
        for (int nt = 0; nt < 8; ++nt)
#pragma unroll
            for (int j = 0; j < 4; ++j) acc[mt][nt][j] = 0.f;

    float4 areg[4], breg[4];

    // prologue: LDG chunk 0 into regs
#pragma unroll
    for (int i = 0; i < 4; ++i) {
        int idx = tid + (i << 8);
        int r = idx >> 3, kk = (idx & 7) << 2;
        areg[i] = *reinterpret_cast<const float4*>(A + (size_t)r * lda + kk);
        if (BT) {
            breg[i] = *reinterpret_cast<const float4*>(B + (size_t)r * ldb + kk);
        } else {
            int rb = idx >> 5, n = (idx & 31) << 2;
            breg[i] = *reinterpret_cast<const float4*>(B + (size_t)rb * ldb + n);
        }
    }

    for (int c = 0; c < nChunks; ++c) {
        uint32_t* As = Asb[c & 1];
        uint32_t* Bs = Bsb[c & 1];
        // commit staged chunk to smem (tf32-converted)
#pragma unroll
        for (int i = 0; i < 4; ++i) {
            int idx = tid + (i << 8);
            int r = idx >> 3, kk = (idx & 7) << 2;
            As[r * 36 + kk + 0] = f2tf32(areg[i].x);
            As[r * 36 + kk + 1] = f2tf32(areg[i].y);
            As[r * 36 + kk + 2] = f2tf32(areg[i].z);
            As[r * 36 + kk + 3] = f2tf32(areg[i].w);
            if (BT) {
                Bs[r * 36 + kk + 0] = f2tf32(breg[i].x);
                Bs[r * 36 + kk + 1] = f2tf32(breg[i].y);
                Bs[r * 36 + kk + 2] = f2tf32(breg[i].z);
                Bs[r * 36 + kk + 3] = f2tf32(breg[i].w);
            } else {
                int rb = idx >> 5, n = (idx & 31) << 2;
                Bs[rb * 132 + n + 0] = f2tf32(breg[i].x);
                Bs[rb * 132 + n + 1] = f2tf32(breg[i].y);
                Bs[rb * 132 + n + 2] = f2tf32(breg[i].z);
                Bs[rb * 132 + n + 3] = f2tf32(breg[i].w);
            }
        }
        __syncthreads();

        // prefetch next chunk into regs while computing this one
        if (c + 1 < nChunks) {
            const float* An = A + (c + 1) * 32;
            const float* Bn = BT ? (B + (c + 1) * 32) : (B + (size_t)((c + 1) * 32) * ldb);
#pragma unroll
            for (int i = 0; i < 4; ++i) {
                int idx = tid + (i << 8);
                int r = idx >> 3, kk = (idx & 7) << 2;
                areg[i] = *reinterpret_cast<const float4*>(An + (size_t)r * lda + kk);
                if (BT) {
                    breg[i] = *reinterpret_cast<const float4*>(Bn + (size_t)r * ldb + kk);
                } else {
                    int rb = idx >> 5, n = (idx & 31) << 2;
                    breg[i] = *reinterpret_cast<const float4*>(Bn + (size_t)rb * ldb + n);
                }
            }
        }

        // compute: 4 k-steps of 8
#pragma unroll
        for (int ks = 0; ks < 4; ++ks) {
            const int kb = ks << 3;
            uint32_t af[2][4];
#pragma unroll
            for (int mt = 0; mt < 2; ++mt) {
                int m = wm * 32 + mt * 16;
                af[mt][0] = As[(m + g) * 36 + kb + t];
                af[mt][1] = As[(m + g + 8) * 36 + kb + t];
                af[mt][2] = As[(m + g) * 36 + kb + t + 4];
                af[mt][3] = As[(m + g + 8) * 36 + kb + t + 4];
            }
#pragma unroll
            for (int nt = 0; nt < 8; ++nt) {
                int n = wn * 64 + nt * 8;
                uint32_t b0, b1;
                if (BT) {
                    b0 = Bs[(n + g) * 36 + kb + t];
                    b1 = Bs[(n + g) * 36 + kb + t + 4];
                } else {
                    b0 = Bs[(kb + t) * 132 + n + g];
                    b1 = Bs[(kb + t + 4) * 132 + n + g];
                }
                mma_tf32(acc[0][nt], af[0], b0, b1);
                mma_tf32(acc[1][nt], af[1], b0, b1);
            }
        }
        // no trailing sync: next STS targets the other buffer; the sync at the
        // top of the next iteration orders reuse two iterations out.
    }

    if (MODE == 1) {
        const float scale = 0.08838834764831845f;   // 1/sqrt(128)
        float rp[4] = {0.f, 0.f, 0.f, 0.f};         // [mt*2 + half] row partials
#pragma unroll
        for (int mt = 0; mt < 2; ++mt)
#pragma unroll
            for (int nt = 0; nt < 8; ++nt)
#pragma unroll
                for (int j = 0; j < 4; ++j) {
                    int lr = wm * 32 + mt * 16 + g + ((j >> 1) << 3);
                    int cg = colg0 + wn * 64 + nt * 8 + (t << 1) + (j & 1);
                    int rg = rowg0 + lr;
                    float e = (cg <= rg) ? expf(acc[mt][nt][j] * scale) : 0.f;
                    acc[mt][nt][j] = e;
                    rp[mt * 2 + (j >> 1)] += e;
                }
#pragma unroll
        for (int i = 0; i < 4; ++i) {
            rp[i] += __shfl_xor_sync(0xffffffffu, rp[i], 1);
            rp[i] += __shfl_xor_sync(0xffffffffu, rp[i], 2);
        }
        __syncthreads();                            // mainloop smem reads done
        float* part = reinterpret_cast<float*>(sm); // [2][128]
        if (t == 0) {
#pragma unroll
            for (int mt = 0; mt < 2; ++mt)
#pragma unroll
                for (int h2 = 0; h2 < 2; ++h2)
                    part[wn * 128 + wm * 32 + mt * 16 + g + (h2 << 3)] = rp[mt * 2 + h2];
        }
        __syncthreads();
        if (tid < 128) partialOut[tid] = part[tid] + part[128 + tid];
    }
    if (MODE == 2) {
#pragma unroll
        for (int mt = 0; mt < 2; ++mt) {
            float i0 = invsum[wm * 32 + mt * 16 + g];
            float i1 = invsum[wm * 32 + mt * 16 + g + 8];
#pragma unroll
            for (int nt = 0; nt < 8; ++nt) {
                acc[mt][nt][0] *= i0; acc[mt][nt][1] *= i0;
                acc[mt][nt][2] *= i1; acc[mt][nt][3] *= i1;
            }
        }
    }

    // epilogue store
#pragma unroll
    for (int mt = 0; mt < 2; ++mt)
#pragma unroll
        for (int nt = 0; nt < 8; ++nt) {
            int row = wm * 32 + mt * 16 + g;
            int col = wn * 64 + nt * 8 + (t << 1);
            *reinterpret_cast<float2*>(C + (size_t)row * ldc + col) =
                make_float2(acc[mt][nt][0], acc[mt][nt][1]);
            *reinterpret_cast<float2*>(C + (size_t)(row + 8) * ldc + col) =
                make_float2(acc[mt][nt][2], acc[mt][nt][3]);
        }
}

// ---- Q projection ----------------------------------------------------------
__global__ void __launch_bounds__(256, 2)
proj_q_kernel(const float* __restrict__ X, const float* __restrict__ Wq)
{
    const int brow = blockIdx.y << 7, bcol = blockIdx.x << 7;
    tf32gemm<false, 0>(X + (size_t)brow * DMODEL, Wq + bcol,
                       g_Q + (size_t)brow * DMODEL + bcol,
                       DMODEL / 32, DMODEL, DMODEL, DMODEL, nullptr, nullptr, 0, 0);
}

// ---- K / V projections -----------------------------------------------------
__global__ void __launch_bounds__(256, 2)
proj_kv_kernel(const float* __restrict__ X,
               const float* __restrict__ Wk,
               const float* __restrict__ Wv)
{
    const int brow = blockIdx.y << 7, bcol = blockIdx.x << 7;
    const float* W = (blockIdx.z == 0) ? Wk : Wv;
    float* O       = (blockIdx.z == 0) ? g_K : g_V;
    tf32gemm<false, 0>(X + (size_t)brow * DMODEL, W + bcol,
                       O + (size_t)brow * KVD + bcol,
                       DMODEL / 32, DMODEL, KVD, KVD, nullptr, nullptr, 0, 0);
}

// ---- RoPE (interleaved), in place on g_Q and g_K ---------------------------
__global__ void rope_kernel()
{
    int idx = blockIdx.x * blockDim.x + threadIdx.x;
    const int qpairs = NTOK * (DMODEL / 2);
    float* ptr;
    int t, p;
    if (idx < qpairs) {
        t = idx >> 10; int c = idx & 1023; p = c & 63;
        ptr = g_Q + (size_t)t * DMODEL + (c << 1);
    } else {
        idx -= qpairs;
        if (idx >= NTOK * (KVD / 2)) return;
        t = idx >> 8; int c = idx & 255; p = c & 63;
        ptr = g_K + (size_t)t * KVD + (c << 1);
    }
    double inv = exp(-(double)p * (9.210340371976184 / 64.0));
    float ang = (float)((double)t * inv);
    float cs = cosf(ang), sn = sinf(ang);
    float xe = ptr[0], xo = ptr[1];
    ptr[0] = xe * cs - xo * sn;
    ptr[1] = xe * sn + xo * cs;
}

// ---- scores + exp + row partials: P[h] = exp(scale * Q K^T) (masked) -------
__global__ void __launch_bounds__(256, 2)
qk_kernel()
{
    if (blockIdx.x > blockIdx.y) return;
    const int h = blockIdx.z, brow = blockIdx.y << 7, bcol = blockIdx.x << 7;
    const int kvh = h >> 2, gs = h & 3;
    tf32gemm<true, 1>(g_Q + (size_t)brow * DMODEL + gs * 512 + kvh * 128,
                      g_K + (size_t)bcol * KVD + kvh * 128,
                      g_S + (size_t)h * NTOK * NTOK + (size_t)brow * NTOK + bcol,
                      HDIM / 32, DMODEL, KVD, NTOK,
                      g_partial + ((size_t)h * 16 + blockIdx.x) * NTOK + brow,
                      nullptr, brow, bcol);
}

// ---- reduce per-tile partials to 1/rowsum ----------------------------------
__global__ void __launch_bounds__(256)
rowsum_kernel()
{
    const int idx = blockIdx.x * 256 + threadIdx.x;   // 0..32767
    const int h = idx >> 11, row = idx & 2047;
    const int ntile = (row >> 7) + 1;
    float s = 0.f;
    for (int tt = 0; tt < ntile; ++tt)
        s += g_partial[((size_t)h * 16 + tt) * NTOK + row];
    g_inv[idx] = 1.f / s;
}

// ---- context: C_h = (P_h @ V_h) * inv[row], K truncated at causal limit ----
__global__ void __launch_bounds__(256, 2)
pv_kernel()
{
    const int h = blockIdx.z, brow = blockIdx.y << 7;
    const int kvh = h >> 2;
    tf32gemm<false, 2>(g_S + (size_t)h * NTOK * NTOK + (size_t)brow * NTOK,
                       g_V + kvh * 128,
                       g_C + (size_t)brow * DMODEL + h * 128,
                       (brow + 128) / 32, NTOK, KVD, DMODEL,
                       nullptr, g_inv + h * NTOK + brow, 0, 0);
}

// ---- output projection: out = ctx @ Wo -------------------------------------
__global__ void __launch_bounds__(256, 2)
out_kernel(const float* __restrict__ Wo, float* __restrict__ out)
{
    const int brow = blockIdx.y << 7, bcol = blockIdx.x << 7;
    tf32gemm<false, 0>(g_C + (size_t)brow * DMODEL, Wo + bcol,
                       out + (size_t)brow * DMODEL + bcol,
                       DMODEL / 32, DMODEL, DMODEL, DMODEL, nullptr, nullptr, 0, 0);
}

extern "C" void kernel_launch(void* const* d_in, const int* in_sizes, int n_in,
                              void* d_out, int out_size)
{
    (void)in_sizes; (void)n_in; (void)out_size;
    const float* x  = (const float*)d_in[0];
    const float* Wq = (const float*)d_in[1];
    const float* Wk = (const float*)d_in[2];
    const float* Wv = (const float*)d_in[3];
    const float* Wo = (const float*)d_in[4];
    float* out = (float*)d_out;

    static int attr_done = 0;
    if (!attr_done) {
        cudaFuncSetAttribute(proj_q_kernel,  cudaFuncAttributeMaxDynamicSharedMemorySize, SMEM_BYTES);
        cudaFuncSetAttribute(proj_kv_kernel, cudaFuncAttributeMaxDynamicSharedMemorySize, SMEM_BYTES);
        cudaFuncSetAttribute(qk_kernel,      cudaFuncAttributeMaxDynamicSharedMemorySize, SMEM_BYTES);
        cudaFuncSetAttribute(pv_kernel,      cudaFuncAttributeMaxDynamicSharedMemorySize, SMEM_BYTES);
        cudaFuncSetAttribute(out_kernel,     cudaFuncAttributeMaxDynamicSharedMemorySize, SMEM_BYTES);
        attr_done = 1;
    }

    proj_q_kernel<<<dim3(DMODEL / 128, NTOK / 128), 256, SMEM_BYTES>>>(x, Wq);
    proj_kv_kernel<<<dim3(KVD / 128, NTOK / 128, 2), 256, SMEM_BYTES>>>(x, Wk, Wv);

    const int total_pairs = NTOK * (DMODEL / 2) + NTOK * (KVD / 2);
    rope_kernel<<<(total_pairs + 255) / 256, 256>>>();

    qk_kernel<<<dim3(NTOK / 128, NTOK / 128, NHEADS), 256, SMEM_BYTES>>>();
    rowsum_kernel<<<NHEADS * NTOK / 256, 256>>>();
    pv_kernel<<<dim3(1, NTOK / 128, NHEADS), 256, SMEM_BYTES>>>();
    out_kernel<<<dim3(DMODEL / 128, NTOK / 128), 256, SMEM_BYTES>>>(Wo, out);
}

// round 6
// speedup vs baseline: 1.8947x; 1.8947x over previous
#include <cuda_runtime.h>
#include <math.h>
#include <stdint.h>

#define NTOK   2048
#define DMODEL 2048
#define KVD    512
#define NHEADS 16
#define HDIM   128

static __device__ float g_Q[NTOK * DMODEL];
static __device__ float g_K[NTOK * KVD];
static __device__ float g_V[NTOK * KVD];
static __device__ float g_S[(size_t)NHEADS * NTOK * NTOK];
static __device__ float g_C[NTOK * DMODEL];
static __device__ float g_partial[(size_t)NHEADS * 16 * NTOK];  // (head, coltile, row)
static __device__ float g_inv[NHEADS * NTOK];                   // 1/rowsum

__device__ __forceinline__ uint32_t f2tf32(float x) {
    uint32_t r;
    asm("cvt.rna.tf32.f32 %0, %1;" : "=r"(r) : "f"(x));
    return r;
}

__device__ __forceinline__ void mma_tf32(float c[4], const uint32_t a[4],
                                         uint32_t b0, uint32_t b1) {
    asm volatile(
        "mma.sync.aligned.m16n8k8.row.col.f32.tf32.tf32.f32 "
        "{%0,%1,%2,%3}, {%4,%5,%6,%7}, {%8,%9}, {%0,%1,%2,%3};"
        : "+f"(c[0]), "+f"(c[1]), "+f"(c[2]), "+f"(c[3])
        : "r"(a[0]), "r"(a[1]), "r"(a[2]), "r"(a[3]), "r"(b0), "r"(b1));
}

// ---------------------------------------------------------------------------
// TF32 tensor-core GEMM (identical mainloop to the proven 797us version).
// 128x128 block tile, 256 threads (8 warps, 4m x 2n), warp tile 32x64,
// K chunk 32, register-staged prefetch, static smem.
// MODE 0: plain store. MODE 1 (qk): exp(scale*acc) + causal mask + row
// partial sums. MODE 2 (pv): acc *= invsum[localrow].
// ---------------------------------------------------------------------------
template <bool BT, int MODE>
__device__ __forceinline__ void tf32gemm(const float* __restrict__ A,
                                         const float* __restrict__ B,
                                         float* __restrict__ C,
                                         int Kdim, int lda, int ldb, int ldc,
                                         float* __restrict__ partialOut,
                                         const float* __restrict__ invsum,
                                         int rowg0, int colg0)
{
    __shared__ uint32_t As[128 * 36];
    __shared__ uint32_t Bs[BT ? (128 * 36) : (32 * 132)];
    __shared__ float part[256];                      // MODE 1 only
    const int tid  = threadIdx.x;
    const int lane = tid & 31, wid = tid >> 5;
    const int wm = wid & 3, wn = wid >> 2;
    const int g = lane >> 2, t = lane & 3;

    float acc[2][8][4];
#pragma unroll
    for (int mt = 0; mt < 2; ++mt)
#pragma unroll
        for (int nt = 0; nt < 8; ++nt)
#pragma unroll
            for (int j = 0; j < 4; ++j) acc[mt][nt][j] = 0.f;

    float4 areg[4], breg[4];

    // prologue: stage chunk 0
#pragma unroll
    for (int i = 0; i < 4; ++i) {
        int idx = tid + (i << 8);
        int r = idx >> 3, kk = (idx & 7) << 2;
        areg[i] = *reinterpret_cast<const float4*>(A + (size_t)r * lda + kk);
        if (BT) {
            breg[i] = *reinterpret_cast<const float4*>(B + (size_t)r * ldb + kk);
        } else {
            int rb = idx >> 5, n = (idx & 31) << 2;
            breg[i] = *reinterpret_cast<const float4*>(B + (size_t)rb * ldb + n);
        }
    }

    for (int k0 = 0; k0 < Kdim; k0 += 32) {
        // commit staged chunk to smem (tf32-converted)
#pragma unroll
        for (int i = 0; i < 4; ++i) {
            int idx = tid + (i << 8);
            int r = idx >> 3, kk = (idx & 7) << 2;
            As[r * 36 + kk + 0] = f2tf32(areg[i].x);
            As[r * 36 + kk + 1] = f2tf32(areg[i].y);
            As[r * 36 + kk + 2] = f2tf32(areg[i].z);
            As[r * 36 + kk + 3] = f2tf32(areg[i].w);
            if (BT) {
                Bs[r * 36 + kk + 0] = f2tf32(breg[i].x);
                Bs[r * 36 + kk + 1] = f2tf32(breg[i].y);
                Bs[r * 36 + kk + 2] = f2tf32(breg[i].z);
                Bs[r * 36 + kk + 3] = f2tf32(breg[i].w);
            } else {
                int rb = idx >> 5, n = (idx & 31) << 2;
                Bs[rb * 132 + n + 0] = f2tf32(breg[i].x);
                Bs[rb * 132 + n + 1] = f2tf32(breg[i].y);
                Bs[rb * 132 + n + 2] = f2tf32(breg[i].z);
                Bs[rb * 132 + n + 3] = f2tf32(breg[i].w);
            }
        }
        __syncthreads();

        // prefetch next chunk while computing this one
        if (k0 + 32 < Kdim) {
            const float* An = A + k0 + 32;
            const float* Bn = BT ? (B + k0 + 32) : (B + (size_t)(k0 + 32) * ldb);
#pragma unroll
            for (int i = 0; i < 4; ++i) {
                int idx = tid + (i << 8);
                int r = idx >> 3, kk = (idx & 7) << 2;
                areg[i] = *reinterpret_cast<const float4*>(An + (size_t)r * lda + kk);
                if (BT) {
                    breg[i] = *reinterpret_cast<const float4*>(Bn + (size_t)r * ldb + kk);
                } else {
                    int rb = idx >> 5, n = (idx & 31) << 2;
                    breg[i] = *reinterpret_cast<const float4*>(Bn + (size_t)rb * ldb + n);
                }
            }
        }

        // compute: 4 k-steps of 8
#pragma unroll
        for (int ks = 0; ks < 4; ++ks) {
            const int kb = ks << 3;
            uint32_t af[2][4];
#pragma unroll
            for (int mt = 0; mt < 2; ++mt) {
                int m = wm * 32 + mt * 16;
                af[mt][0] = As[(m + g) * 36 + kb + t];
                af[mt][1] = As[(m + g + 8) * 36 + kb + t];
                af[mt][2] = As[(m + g) * 36 + kb + t + 4];
                af[mt][3] = As[(m + g + 8) * 36 + kb + t + 4];
            }
#pragma unroll
            for (int nt = 0; nt < 8; ++nt) {
                int n = wn * 64 + nt * 8;
                uint32_t b0, b1;
                if (BT) {
                    b0 = Bs[(n + g) * 36 + kb + t];
                    b1 = Bs[(n + g) * 36 + kb + t + 4];
                } else {
                    b0 = Bs[(kb + t) * 132 + n + g];
                    b1 = Bs[(kb + t + 4) * 132 + n + g];
                }
                mma_tf32(acc[0][nt], af[0], b0, b1);
                mma_tf32(acc[1][nt], af[1], b0, b1);
            }
        }
        __syncthreads();
    }

    if (MODE == 1) {
        const float scale = 0.08838834764831845f;   // 1/sqrt(128)
        float rp[4] = {0.f, 0.f, 0.f, 0.f};         // [mt*2 + half]
#pragma unroll
        for (int mt = 0; mt < 2; ++mt)
#pragma unroll
            for (int nt = 0; nt < 8; ++nt)
#pragma unroll
                for (int j = 0; j < 4; ++j) {
                    int lr = wm * 32 + mt * 16 + g + ((j >> 1) << 3);
                    int cg = colg0 + wn * 64 + nt * 8 + (t << 1) + (j & 1);
                    int rg = rowg0 + lr;
                    float e = (cg <= rg) ? expf(acc[mt][nt][j] * scale) : 0.f;
                    acc[mt][nt][j] = e;
                    rp[mt * 2 + (j >> 1)] += e;
                }
#pragma unroll
        for (int i = 0; i < 4; ++i) {
            rp[i] += __shfl_xor_sync(0xffffffffu, rp[i], 1);
            rp[i] += __shfl_xor_sync(0xffffffffu, rp[i], 2);
        }
        if (t == 0) {
#pragma unroll
            for (int mt = 0; mt < 2; ++mt)
#pragma unroll
                for (int h2 = 0; h2 < 2; ++h2)
                    part[wn * 128 + wm * 32 + mt * 16 + g + (h2 << 3)] = rp[mt * 2 + h2];
        }
        __syncthreads();
        if (tid < 128) partialOut[tid] = part[tid] + part[128 + tid];
    }
    if (MODE == 2) {
#pragma unroll
        for (int mt = 0; mt < 2; ++mt) {
            float i0 = invsum[wm * 32 + mt * 16 + g];
            float i1 = invsum[wm * 32 + mt * 16 + g + 8];
#pragma unroll
            for (int nt = 0; nt < 8; ++nt) {
                acc[mt][nt][0] *= i0; acc[mt][nt][1] *= i0;
                acc[mt][nt][2] *= i1; acc[mt][nt][3] *= i1;
            }
        }
    }

    // epilogue store
#pragma unroll
    for (int mt = 0; mt < 2; ++mt)
#pragma unroll
        for (int nt = 0; nt < 8; ++nt) {
            int row = wm * 32 + mt * 16 + g;
            int col = wn * 64 + nt * 8 + (t << 1);
            *reinterpret_cast<float2*>(C + (size_t)row * ldc + col) =
                make_float2(acc[mt][nt][0], acc[mt][nt][1]);
            *reinterpret_cast<float2*>(C + (size_t)(row + 8) * ldc + col) =
                make_float2(acc[mt][nt][2], acc[mt][nt][3]);
        }
}

// ---- Q projection ----------------------------------------------------------
__global__ void __launch_bounds__(256, 2)
proj_q_kernel(const float* __restrict__ X, const float* __restrict__ Wq)
{
    const int brow = blockIdx.y << 7, bcol = blockIdx.x << 7;
    tf32gemm<false, 0>(X + (size_t)brow * DMODEL, Wq + bcol,
                       g_Q + (size_t)brow * DMODEL + bcol,
                       DMODEL, DMODEL, DMODEL, DMODEL, nullptr, nullptr, 0, 0);
}

// ---- K / V projections -----------------------------------------------------
__global__ void __launch_bounds__(256, 2)
proj_kv_kernel(const float* __restrict__ X,
               const float* __restrict__ Wk,
               const float* __restrict__ Wv)
{
    const int brow = blockIdx.y << 7, bcol = blockIdx.x << 7;
    const float* W = (blockIdx.z == 0) ? Wk : Wv;
    float* O       = (blockIdx.z == 0) ? g_K : g_V;
    tf32gemm<false, 0>(X + (size_t)brow * DMODEL, W + bcol,
                       O + (size_t)brow * KVD + bcol,
                       DMODEL, DMODEL, KVD, KVD, nullptr, nullptr, 0, 0);
}

// ---- RoPE (interleaved), in place on g_Q and g_K ---------------------------
__global__ void rope_kernel()
{
    int idx = blockIdx.x * blockDim.x + threadIdx.x;
    const int qpairs = NTOK * (DMODEL / 2);
    float* ptr;
    int t, p;
    if (idx < qpairs) {
        t = idx >> 10; int c = idx & 1023; p = c & 63;
        ptr = g_Q + (size_t)t * DMODEL + (c << 1);
    } else {
        idx -= qpairs;
        if (idx >= NTOK * (KVD / 2)) return;
        t = idx >> 8; int c = idx & 255; p = c & 63;
        ptr = g_K + (size_t)t * KVD + (c << 1);
    }
    double inv = exp(-(double)p * (9.210340371976184 / 64.0));
    float ang = (float)((double)t * inv);
    float cs = cosf(ang), sn = sinf(ang);
    float xe = ptr[0], xo = ptr[1];
    ptr[0] = xe * cs - xo * sn;
    ptr[1] = xe * sn + xo * cs;
}

// ---- scores + exp + row partials -------------------------------------------
__global__ void __launch_bounds__(256, 2)
qk_kernel()
{
    if (blockIdx.x > blockIdx.y) return;
    const int h = blockIdx.z, brow = blockIdx.y << 7, bcol = blockIdx.x << 7;
    const int kvh = h >> 2, gs = h & 3;
    tf32gemm<true, 1>(g_Q + (size_t)brow * DMODEL + gs * 512 + kvh * 128,
                      g_K + (size_t)bcol * KVD + kvh * 128,
                      g_S + (size_t)h * NTOK * NTOK + (size_t)brow * NTOK + bcol,
                      HDIM, DMODEL, KVD, NTOK,
                      g_partial + ((size_t)h * 16 + blockIdx.x) * NTOK + brow,
                      nullptr, brow, bcol);
}

// ---- reduce per-tile partials to 1/rowsum ----------------------------------
__global__ void __launch_bounds__(256)
rowsum_kernel()
{
    const int idx = blockIdx.x * 256 + threadIdx.x;   // 0..32767
    const int h = idx >> 11, row = idx & 2047;
    const int ntile = (row >> 7) + 1;
    float s = 0.f;
    for (int tt = 0; tt < ntile; ++tt)
        s += g_partial[((size_t)h * 16 + tt) * NTOK + row];
    g_inv[idx] = 1.f / s;
}

// ---- context: C_h = (P_h @ V_h) * inv[row] ---------------------------------
__global__ void __launch_bounds__(256, 2)
pv_kernel()
{
    const int h = blockIdx.z, brow = blockIdx.y << 7;
    const int kvh = h >> 2;
    tf32gemm<false, 2>(g_S + (size_t)h * NTOK * NTOK + (size_t)brow * NTOK,
                       g_V + kvh * 128,
                       g_C + (size_t)brow * DMODEL + h * 128,
                       brow + 128, NTOK, KVD, DMODEL,
                       nullptr, g_inv + h * NTOK + brow, 0, 0);
}

// ---- output projection -----------------------------------------------------
__global__ void __launch_bounds__(256, 2)
out_kernel(const float* __restrict__ Wo, float* __restrict__ out)
{
    const int brow = blockIdx.y << 7, bcol = blockIdx.x << 7;
    tf32gemm<false, 0>(g_C + (size_t)brow * DMODEL, Wo + bcol,
                       out + (size_t)brow * DMODEL + bcol,
                       DMODEL, DMODEL, DMODEL, DMODEL, nullptr, nullptr, 0, 0);
}

extern "C" void kernel_launch(void* const* d_in, const int* in_sizes, int n_in,
                              void* d_out, int out_size)
{
    (void)in_sizes; (void)n_in; (void)out_size;
    const float* x  = (const float*)d_in[0];
    const float* Wq = (const float*)d_in[1];
    const float* Wk = (const float*)d_in[2];
    const float* Wv = (const float*)d_in[3];
    const float* Wo = (const float*)d_in[4];
    float* out = (float*)d_out;

    proj_q_kernel<<<dim3(DMODEL / 128, NTOK / 128), 256>>>(x, Wq);
    proj_kv_kernel<<<dim3(KVD / 128, NTOK / 128, 2), 256>>>(x, Wk, Wv);

    const int total_pairs = NTOK * (DMODEL / 2) + NTOK * (KVD / 2);
    rope_kernel<<<(total_pairs + 255) / 256, 256>>>();

    qk_kernel<<<dim3(NTOK / 128, NTOK / 128, NHEADS), 256>>>();
    rowsum_kernel<<<NHEADS * NTOK / 256, 256>>>();
    pv_kernel<<<dim3(1, NTOK / 128, NHEADS), 256>>>();
    out_kernel<<<dim3(DMODEL / 128, NTOK / 128), 256>>>(Wo, out);
}

// round 7
// speedup vs baseline: 2.0521x; 1.0831x over previous
#include <cuda_runtime.h>
#include <math.h>
#include <stdint.h>

#define NTOK   2048
#define DMODEL 2048
#define KVD    512
#define NHEADS 16
#define HDIM   128

static __device__ float g_Q[NTOK * DMODEL];
static __device__ float g_K[NTOK * KVD];
static __device__ float g_V[NTOK * KVD];
static __device__ float g_S[(size_t)NHEADS * NTOK * NTOK];
static __device__ float g_C[NTOK * DMODEL];
static __device__ float g_partial[(size_t)NHEADS * 16 * NTOK];  // (head, coltile, row)
static __device__ float g_inv[NHEADS * NTOK];                   // 1/rowsum

#define BSN 136   // NN B-tile row stride (words); 136 % 32 == 8 -> conflict-free

__device__ __forceinline__ uint32_t f2tf32(float x) {
    uint32_t r;
    asm("cvt.rna.tf32.f32 %0, %1;" : "=r"(r) : "f"(x));
    return r;
}

__device__ __forceinline__ void mma_tf32(float c[4], const uint32_t a[4],
                                         uint32_t b0, uint32_t b1) {
    asm volatile(
        "mma.sync.aligned.m16n8k8.row.col.f32.tf32.tf32.f32 "
        "{%0,%1,%2,%3}, {%4,%5,%6,%7}, {%8,%9}, {%0,%1,%2,%3};"
        : "+f"(c[0]), "+f"(c[1]), "+f"(c[2]), "+f"(c[3])
        : "r"(a[0]), "r"(a[1]), "r"(a[2]), "r"(a[3]), "r"(b0), "r"(b1));
}

// ---------------------------------------------------------------------------
// TF32 tensor-core GEMM. 128x128 block tile, 256 threads (8 warps, 4m x 2n),
// warp tile 32x64, K chunk 32, register-staged prefetch, static smem.
// MODE 0: plain store. MODE 1 (qk): exp(scale*acc) + causal mask + row
// partial sums. MODE 2 (pv): acc *= invsum[localrow].
// ---------------------------------------------------------------------------
template <bool BT, int MODE>
__device__ __forceinline__ void tf32gemm(const float* __restrict__ A,
                                         const float* __restrict__ B,
                                         float* __restrict__ C,
                                         int Kdim, int lda, int ldb, int ldc,
                                         float* __restrict__ partialOut,
                                         const float* __restrict__ invsum,
                                         int rowg0, int colg0)
{
    __shared__ uint32_t As[128 * 36];
    __shared__ uint32_t Bs[BT ? (128 * 36) : (32 * BSN)];
    __shared__ float part[256];                      // MODE 1 only
    const int tid  = threadIdx.x;
    const int lane = tid & 31, wid = tid >> 5;
    const int wm = wid & 3, wn = wid >> 2;
    const int g = lane >> 2, t = lane & 3;

    float acc[2][8][4];
#pragma unroll
    for (int mt = 0; mt < 2; ++mt)
#pragma unroll
        for (int nt = 0; nt < 8; ++nt)
#pragma unroll
            for (int j = 0; j < 4; ++j) acc[mt][nt][j] = 0.f;

    float4 areg[4], breg[4];

    // prologue: stage chunk 0
#pragma unroll
    for (int i = 0; i < 4; ++i) {
        int idx = tid + (i << 8);
        int r = idx >> 3, kk = (idx & 7) << 2;
        areg[i] = *reinterpret_cast<const float4*>(A + (size_t)r * lda + kk);
        if (BT) {
            breg[i] = *reinterpret_cast<const float4*>(B + (size_t)r * ldb + kk);
        } else {
            int rb = idx >> 5, n = (idx & 31) << 2;
            breg[i] = *reinterpret_cast<const float4*>(B + (size_t)rb * ldb + n);
        }
    }

    for (int k0 = 0; k0 < Kdim; k0 += 32) {
        // commit staged chunk to smem (tf32-converted)
#pragma unroll
        for (int i = 0; i < 4; ++i) {
            int idx = tid + (i << 8);
            int r = idx >> 3, kk = (idx & 7) << 2;
            As[r * 36 + kk + 0] = f2tf32(areg[i].x);
            As[r * 36 + kk + 1] = f2tf32(areg[i].y);
            As[r * 36 + kk + 2] = f2tf32(areg[i].z);
            As[r * 36 + kk + 3] = f2tf32(areg[i].w);
            if (BT) {
                Bs[r * 36 + kk + 0] = f2tf32(breg[i].x);
                Bs[r * 36 + kk + 1] = f2tf32(breg[i].y);
                Bs[r * 36 + kk + 2] = f2tf32(breg[i].z);
                Bs[r * 36 + kk + 3] = f2tf32(breg[i].w);
            } else {
                int rb = idx >> 5, n = (idx & 31) << 2;
                Bs[rb * BSN + n + 0] = f2tf32(breg[i].x);
                Bs[rb * BSN + n + 1] = f2tf32(breg[i].y);
                Bs[rb * BSN + n + 2] = f2tf32(breg[i].z);
                Bs[rb * BSN + n + 3] = f2tf32(breg[i].w);
            }
        }
        __syncthreads();

        // prefetch next chunk while computing this one
        if (k0 + 32 < Kdim) {
            const float* An = A + k0 + 32;
            const float* Bn = BT ? (B + k0 + 32) : (B + (size_t)(k0 + 32) * ldb);
#pragma unroll
            for (int i = 0; i < 4; ++i) {
                int idx = tid + (i << 8);
                int r = idx >> 3, kk = (idx & 7) << 2;
                areg[i] = *reinterpret_cast<const float4*>(An + (size_t)r * lda + kk);
                if (BT) {
                    breg[i] = *reinterpret_cast<const float4*>(Bn + (size_t)r * ldb + kk);
                } else {
                    int rb = idx >> 5, n = (idx & 31) << 2;
                    breg[i] = *reinterpret_cast<const float4*>(Bn + (size_t)rb * ldb + n);
                }
            }
        }

        // compute: 4 k-steps of 8
#pragma unroll
        for (int ks = 0; ks < 4; ++ks) {
            const int kb = ks << 3;
            uint32_t af[2][4];
#pragma unroll
            for (int mt = 0; mt < 2; ++mt) {
                int m = wm * 32 + mt * 16;
                af[mt][0] = As[(m + g) * 36 + kb + t];
                af[mt][1] = As[(m + g + 8) * 36 + kb + t];
                af[mt][2] = As[(m + g) * 36 + kb + t + 4];
                af[mt][3] = As[(m + g + 8) * 36 + kb + t + 4];
            }
#pragma unroll
            for (int nt = 0; nt < 8; ++nt) {
                int n = wn * 64 + nt * 8;
                uint32_t b0, b1;
                if (BT) {
                    b0 = Bs[(n + g) * 36 + kb + t];
                    b1 = Bs[(n + g) * 36 + kb + t + 4];
                } else {
                    b0 = Bs[(kb + t) * BSN + n + g];
                    b1 = Bs[(kb + t + 4) * BSN + n + g];
                }
                mma_tf32(acc[0][nt], af[0], b0, b1);
                mma_tf32(acc[1][nt], af[1], b0, b1);
            }
        }
        __syncthreads();
    }

    if (MODE == 1) {
        const float scale = 0.08838834764831845f;   // 1/sqrt(128)
        float rp[4] = {0.f, 0.f, 0.f, 0.f};         // [mt*2 + half]
#pragma unroll
        for (int mt = 0; mt < 2; ++mt)
#pragma unroll
            for (int nt = 0; nt < 8; ++nt)
#pragma unroll
                for (int j = 0; j < 4; ++j) {
                    int lr = wm * 32 + mt * 16 + g + ((j >> 1) << 3);
                    int cg = colg0 + wn * 64 + nt * 8 + (t << 1) + (j & 1);
                    int rg = rowg0 + lr;
                    float e = (cg <= rg) ? __expf(acc[mt][nt][j] * scale) : 0.f;
                    acc[mt][nt][j] = e;
                    rp[mt * 2 + (j >> 1)] += e;
                }
#pragma unroll
        for (int i = 0; i < 4; ++i) {
            rp[i] += __shfl_xor_sync(0xffffffffu, rp[i], 1);
            rp[i] += __shfl_xor_sync(0xffffffffu, rp[i], 2);
        }
        if (t == 0) {
#pragma unroll
            for (int mt = 0; mt < 2; ++mt)
#pragma unroll
                for (int h2 = 0; h2 < 2; ++h2)
                    part[wn * 128 + wm * 32 + mt * 16 + g + (h2 << 3)] = rp[mt * 2 + h2];
        }
        __syncthreads();
        if (tid < 128) partialOut[tid] = part[tid] + part[128 + tid];
    }
    if (MODE == 2) {
#pragma unroll
        for (int mt = 0; mt < 2; ++mt) {
            float i0 = invsum[wm * 32 + mt * 16 + g];
            float i1 = invsum[wm * 32 + mt * 16 + g + 8];
#pragma unroll
            for (int nt = 0; nt < 8; ++nt) {
                acc[mt][nt][0] *= i0; acc[mt][nt][1] *= i0;
                acc[mt][nt][2] *= i1; acc[mt][nt][3] *= i1;
            }
        }
    }

    // epilogue store
#pragma unroll
    for (int mt = 0; mt < 2; ++mt)
#pragma unroll
        for (int nt = 0; nt < 8; ++nt) {
            int row = wm * 32 + mt * 16 + g;
            int col = wn * 64 + nt * 8 + (t << 1);
            *reinterpret_cast<float2*>(C + (size_t)row * ldc + col) =
                make_float2(acc[mt][nt][0], acc[mt][nt][1]);
            *reinterpret_cast<float2*>(C + (size_t)(row + 8) * ldc + col) =
                make_float2(acc[mt][nt][2], acc[mt][nt][3]);
        }
}

// ---- Q projection ----------------------------------------------------------
__global__ void __launch_bounds__(256, 2)
proj_q_kernel(const float* __restrict__ X, const float* __restrict__ Wq)
{
    const int brow = blockIdx.y << 7, bcol = blockIdx.x << 7;
    tf32gemm<false, 0>(X + (size_t)brow * DMODEL, Wq + bcol,
                       g_Q + (size_t)brow * DMODEL + bcol,
                       DMODEL, DMODEL, DMODEL, DMODEL, nullptr, nullptr, 0, 0);
}

// ---- K / V projections -----------------------------------------------------
__global__ void __launch_bounds__(256, 2)
proj_kv_kernel(const float* __restrict__ X,
               const float* __restrict__ Wk,
               const float* __restrict__ Wv)
{
    const int brow = blockIdx.y << 7, bcol = blockIdx.x << 7;
    const float* W = (blockIdx.z == 0) ? Wk : Wv;
    float* O       = (blockIdx.z == 0) ? g_K : g_V;
    tf32gemm<false, 0>(X + (size_t)brow * DMODEL, W + bcol,
                       O + (size_t)brow * KVD + bcol,
                       DMODEL, DMODEL, KVD, KVD, nullptr, nullptr, 0, 0);
}

// ---- RoPE (interleaved), in place on g_Q and g_K ---------------------------
__global__ void rope_kernel()
{
    int idx = blockIdx.x * blockDim.x + threadIdx.x;
    const int qpairs = NTOK * (DMODEL / 2);
    float* ptr;
    int t, p;
    if (idx < qpairs) {
        t = idx >> 10; int c = idx & 1023; p = c & 63;
        ptr = g_Q + (size_t)t * DMODEL + (c << 1);
    } else {
        idx -= qpairs;
        if (idx >= NTOK * (KVD / 2)) return;
        t = idx >> 8; int c = idx & 255; p = c & 63;
        ptr = g_K + (size_t)t * KVD + (c << 1);
    }
    double inv = exp(-(double)p * (9.210340371976184 / 64.0));
    float ang = (float)((double)t * inv);
    float cs = cosf(ang), sn = sinf(ang);
    float xe = ptr[0], xo = ptr[1];
    ptr[0] = xe * cs - xo * sn;
    ptr[1] = xe * sn + xo * cs;
}

// ---- scores + exp + row partials -------------------------------------------
__global__ void __launch_bounds__(256, 2)
qk_kernel()
{
    if (blockIdx.x > blockIdx.y) return;
    const int h = blockIdx.z, brow = blockIdx.y << 7, bcol = blockIdx.x << 7;
    const int kvh = h >> 2, gs = h & 3;
    tf32gemm<true, 1>(g_Q + (size_t)brow * DMODEL + gs * 512 + kvh * 128,
                      g_K + (size_t)bcol * KVD + kvh * 128,
                      g_S + (size_t)h * NTOK * NTOK + (size_t)brow * NTOK + bcol,
                      HDIM, DMODEL, KVD, NTOK,
                      g_partial + ((size_t)h * 16 + blockIdx.x) * NTOK + brow,
                      nullptr, brow, bcol);
}

// ---- reduce per-tile partials to 1/rowsum ----------------------------------
__global__ void __launch_bounds__(256)
rowsum_kernel()
{
    const int idx = blockIdx.x * 256 + threadIdx.x;   // 0..32767
    const int h = idx >> 11, row = idx & 2047;
    const int ntile = (row >> 7) + 1;
    float s = 0.f;
    for (int tt = 0; tt < ntile; ++tt)
        s += g_partial[((size_t)h * 16 + tt) * NTOK + row];
    g_inv[idx] = 1.f / s;
}

// ---- context: C_h = (P_h @ V_h) * inv[row] ---------------------------------
__global__ void __launch_bounds__(256, 2)
pv_kernel()
{
    const int h = blockIdx.z, brow = blockIdx.y << 7;
    const int kvh = h >> 2;
    tf32gemm<false, 2>(g_S + (size_t)h * NTOK * NTOK + (size_t)brow * NTOK,
                       g_V + kvh * 128,
                       g_C + (size_t)brow * DMODEL + h * 128,
                       brow + 128, NTOK, KVD, DMODEL,
                       nullptr, g_inv + h * NTOK + brow, 0, 0);
}

// ---- output projection -----------------------------------------------------
__global__ void __launch_bounds__(256, 2)
out_kernel(const float* __restrict__ Wo, float* __restrict__ out)
{
    const int brow = blockIdx.y << 7, bcol = blockIdx.x << 7;
    tf32gemm<false, 0>(g_C + (size_t)brow * DMODEL, Wo + bcol,
                       out + (size_t)brow * DMODEL + bcol,
                       DMODEL, DMODEL, DMODEL, DMODEL, nullptr, nullptr, 0, 0);
}

extern "C" void kernel_launch(void* const* d_in, const int* in_sizes, int n_in,
                              void* d_out, int out_size)
{
    (void)in_sizes; (void)n_in; (void)out_size;
    const float* x  = (const float*)d_in[0];
    const float* Wq = (const float*)d_in[1];
    const float* Wk = (const float*)d_in[2];
    const float* Wv = (const float*)d_in[3];
    const float* Wo = (const float*)d_in[4];
    float* out = (float*)d_out;

    proj_q_kernel<<<dim3(DMODEL / 128, NTOK / 128), 256>>>(x, Wq);
    proj_kv_kernel<<<dim3(KVD / 128, NTOK / 128, 2), 256>>>(x, Wk, Wv);

    const int total_pairs = NTOK * (DMODEL / 2) + NTOK * (KVD / 2);
    rope_kernel<<<(total_pairs + 255) / 256, 256>>>();

    qk_kernel<<<dim3(NTOK / 128, NTOK / 128, NHEADS), 256>>>();
    rowsum_kernel<<<NHEADS * NTOK / 256, 256>>>();
    pv_kernel<<<dim3(1, NTOK / 128, NHEADS), 256>>>();
    out_kernel<<<dim3(DMODEL / 128, NTOK / 128), 256>>>(Wo, out);
}